// round 11
// baseline (speedup 1.0000x reference)
#include <cuda_runtime.h>
#include <cuda_fp16.h>
#include <cstdint>

#define NQ 8
#define DIM 256
#define BATCH 65536
#define NL 8

#define THREADS 128
#define TILE_M 128
#define NTILES (BATCH / TILE_M)     // 512
#define NPER 37                     // CTAs per N-eighth; grid = 296 (2/SM)
#define STRIDE 264                  // smem row stride in halves (256 + 8 pad)

#define M_BYTES (TILE_M * STRIDE * 2)   // 67584
#define B_OFF   M_BYTES
#define B_BYTES (64 * STRIDE * 2)       // 33792
#define SMEM_TOTAL (M_BYTES + B_BYTES)  // 101376  (2 CTAs/SM)

#define COMB_OFF 0                  // float[128][8] = 4 KB (overlay on m)
#define EXCH_OFF 4096               // float4[4][16][32] = 32 KB (overlay on m)

__device__ __align__(16) __half g_Vn2k[512 * 256];   // [n2][k] GEMM B layout

// ---------------------------------------------------------------------------
// Kernel 1: blocks 0..31 = warp-level entangler simulation (one warp = one
// basis column k). Blocks 32..543 zero out[].
// ---------------------------------------------------------------------------
__global__ void build_V_kernel(const float* __restrict__ w, float4* __restrict__ out4) {
    if (blockIdx.x >= 32) {
        out4[(blockIdx.x - 32) * 256 + threadIdx.x] = make_float4(0.f, 0.f, 0.f, 0.f);
        return;
    }
    __shared__ __half tr[8][528];        // [k within block][n2]
    const int t = threadIdx.x;
    const int warp = t >> 5, lane = t & 31;
    const int k = blockIdx.x * 8 + warp;

    float2 a[8];
#pragma unroll
    for (int r = 0; r < 8; r++) {
        const int idx = lane * 8 + r;
        a[r] = make_float2(idx == k ? 1.f : 0.f, 0.f);
    }

    for (int l = 0; l < NL; l++) {
#pragma unroll
        for (int q = 0; q < 8; q++) {
            float s, c, zs, zc;
            __sincosf(0.5f * w[(l * 8 + q) * 2 + 0], &s, &c);
            __sincosf(0.5f * w[(l * 8 + q) * 2 + 1], &zs, &zc);
            const int p = 7 - q;
            if (p < 3) {
                const int bit = 1 << p;
#pragma unroll
                for (int r = 0; r < 8; r++) {
                    if (!(r & bit)) {
                        const float2 a0 = a[r], a1 = a[r | bit];
                        const float xr0 = c * a0.x - s * a1.x;
                        const float xi0 = c * a0.y - s * a1.y;
                        const float xr1 = s * a0.x + c * a1.x;
                        const float xi1 = s * a0.y + c * a1.y;
                        a[r]       = make_float2(zc * xr0 + zs * xi0, zc * xi0 - zs * xr0);
                        a[r | bit] = make_float2(zc * xr1 - zs * xi1, zc * xi1 + zs * xr1);
                    }
                }
            } else {
                const int lm = 1 << (p - 3);
                const bool hi = (lane & lm) != 0;
                const float zss = hi ? -zs : zs;
#pragma unroll
                for (int r = 0; r < 8; r++) {
                    const float ox = __shfl_xor_sync(0xffffffffu, a[r].x, lm);
                    const float oy = __shfl_xor_sync(0xffffffffu, a[r].y, lm);
                    const float xr = hi ? (s * ox + c * a[r].x) : (c * a[r].x - s * ox);
                    const float xi = hi ? (s * oy + c * a[r].y) : (c * a[r].y - s * oy);
                    a[r] = make_float2(zc * xr + zss * xi, zc * xi - zss * xr);
                }
            }
        }
#pragma unroll
        for (int q = 0; q < 8; q++) {
            const int cp = 7 - q, tp = 7 - ((q + 1) & 7);
            if (cp >= 3 && tp >= 3) {
                const int cl = 1 << (cp - 3), tl = 1 << (tp - 3);
#pragma unroll
                for (int r = 0; r < 8; r++) {
                    const float ox = __shfl_xor_sync(0xffffffffu, a[r].x, tl);
                    const float oy = __shfl_xor_sync(0xffffffffu, a[r].y, tl);
                    if (lane & cl) { a[r].x = ox; a[r].y = oy; }
                }
            } else if (cp >= 3) {
                const int cl = 1 << (cp - 3), tb = 1 << tp;
                if (lane & cl) {
#pragma unroll
                    for (int r = 0; r < 8; r++) {
                        if (!(r & tb)) {
                            const float2 tmp = a[r]; a[r] = a[r | tb]; a[r | tb] = tmp;
                        }
                    }
                }
            } else if (tp >= 3) {
                const int cb = 1 << cp, tl = 1 << (tp - 3);
#pragma unroll
                for (int r = 0; r < 8; r++) {
                    const float ox = __shfl_xor_sync(0xffffffffu, a[r].x, tl);
                    const float oy = __shfl_xor_sync(0xffffffffu, a[r].y, tl);
                    if (r & cb) { a[r].x = ox; a[r].y = oy; }
                }
            } else {
                const int cb = 1 << cp, tb = 1 << tp;
#pragma unroll
                for (int r = 0; r < 8; r++) {
                    if ((r & cb) && !(r & tb)) {
                        const float2 tmp = a[r]; a[r] = a[r | tb]; a[r | tb] = tmp;
                    }
                }
            }
        }
    }

    const int pc = __popc(k) & 3;
#pragma unroll
    for (int r = 0; r < 8; r++) {
        const float2 u = a[r];
        float2 vv;
        if      (pc == 0) vv = u;
        else if (pc == 1) vv = make_float2( u.y, -u.x);
        else if (pc == 2) vv = make_float2(-u.x, -u.y);
        else              vv = make_float2(-u.y,  u.x);
        const int n2 = (lane * 8 + r) * 2;
        *(__half2*)&tr[warp][n2] = __floats2half2_rn(vv.x, vv.y);
    }
    __syncthreads();

    const int kb = blockIdx.x * 8;
#pragma unroll
    for (int i = 0; i < 2; i++) {
        const int n2 = 2 * t + i;
        __half tmp[8];
#pragma unroll
        for (int kk = 0; kk < 8; kk++) tmp[kk] = tr[kk][n2];
        *(uint4*)&g_Vn2k[n2 * 256 + kb] = *(uint4*)tmp;
    }
}

// ---------------------------------------------------------------------------
// helpers
// ---------------------------------------------------------------------------
__device__ __forceinline__ uint32_t smem_u32(const void* p) {
    return (uint32_t)__cvta_generic_to_shared(p);
}
__device__ __forceinline__ void cp_async16(uint32_t dst, const void* src) {
    asm volatile("cp.async.cg.shared.global [%0], [%1], 16;" :: "r"(dst), "l"(src));
}
__device__ __forceinline__ void ldsm4(uint32_t r[4], uint32_t addr) {
    asm volatile("ldmatrix.sync.aligned.m8n8.x4.shared.b16 {%0,%1,%2,%3}, [%4];"
                 : "=r"(r[0]), "=r"(r[1]), "=r"(r[2]), "=r"(r[3]) : "r"(addr));
}
__device__ __forceinline__ void mma16816(float4& c, const uint32_t a[4],
                                         uint32_t b0, uint32_t b1) {
    asm volatile(
        "mma.sync.aligned.m16n8k16.row.col.f32.f16.f16.f32 "
        "{%0,%1,%2,%3}, {%4,%5,%6,%7}, {%8,%9}, {%0,%1,%2,%3};"
        : "+f"(c.x), "+f"(c.y), "+f"(c.z), "+f"(c.w)
        : "r"(a[0]), "r"(a[1]), "r"(a[2]), "r"(a[3]), "r"(b0), "r"(b1));
}
__device__ __forceinline__ float red4(float v) {
    v += __shfl_xor_sync(0xffffffffu, v, 1);
    v += __shfl_xor_sync(0xffffffffu, v, 2);
    return v;
}

// ---------------------------------------------------------------------------
// Kernel 2: persistent GEMM, 2 CTAs/SM, K-split warps.
// CTA = 128 threads (4 warps = (mh, kh)), owns one N-eighth (64 n2 rows).
// Sample tile = 128. Warp tile 64 samples x 64 n2 x K=128.
// K-partials exchanged through smem before squaring.
// ---------------------------------------------------------------------------
__global__ __launch_bounds__(THREADS)
void qsim_main_kernel(const float* __restrict__ x, float* __restrict__ out) {
    extern __shared__ __align__(16) char smem[];
    __half* m_sm = (__half*)smem;
    float*  comb = (float*)(smem + COMB_OFF);     // [128][8]
    float4* exch = (float4*)(smem + EXCH_OFF);    // [4 regions][16][32]

    const int t = threadIdx.x;
    const int warp = t >> 5, lane = t & 31;
    const int eighth = blockIdx.x & 7;
    const int idx0 = blockIdx.x >> 3;             // 0..36

    // ---- stage this CTA's B eighth (64 n2-rows x 512B) once ----
    {
        const char* src = (const char*)g_Vn2k + eighth * (64 * 512);
        const uint32_t dst = smem_u32(smem + B_OFF);
#pragma unroll
        for (int i = 0; i < 16; i++) {
            const int e = t + THREADS * i;        // 2048 x 16B
            const int row = e >> 5, c16 = e & 31;
            cp_async16(dst + row * (STRIDE * 2) + c16 * 16,
                       src + row * 512 + c16 * 16);
        }
        asm volatile("cp.async.commit_group;" ::: "memory");
    }

    const uint32_t m_u = smem_u32(m_sm);
    const uint32_t b_u = smem_u32(smem + B_OFF);

    const int mh = warp >> 1;         // 64-sample half of the tile
    const int kh = warp & 1;          // K half (128 each)
    const int gid = lane >> 2, tig = lane & 3;

    const int rowA_off = (mh * 64 + (lane & 7) + 8 * ((lane >> 3) & 1)) * STRIDE
                       + 8 * (lane >> 4) + kh * 128;
    const int rowB_off = (((lane >> 4) & 1) * 8 + (lane & 7)) * STRIDE
                       + 8 * ((lane >> 3) & 1) + kh * 128;

    // sign constants from eighth (n bits 7:5 -> q0,q1,q2)
    const float s0 = (eighth & 4) ? -1.f : 1.f;
    const float s1 = (eighth & 2) ? -1.f : 1.f;
    const float s2 = (eighth & 1) ? -1.f : 1.f;

    bool first = true;
    for (int tile = idx0; tile < NTILES; tile += NPER) {
        // prefetch angles (thread t = sample t of the tile)
        float xv[8];
        {
            const float* xp = x + (size_t)(tile * TILE_M + t) * NQ;
#pragma unroll
            for (int q = 0; q < 8; q++) xv[q] = xp[q];
        }
        __syncthreads();              // prev tile's comb/exch reads done

        // ---- build m tile: thread t -> sample t, all 256 k ----
        {
            float c[8], sn[8];
#pragma unroll
            for (int q = 0; q < 8; q++) {
                float sv, cv;
                __sincosf(0.5f * xv[q], &sv, &cv);
                c[q] = cv; sn[q] = sv;
            }
            float H16[16], L16[16];
#pragma unroll
            for (int h = 0; h < 16; h++)
                H16[h] = ((h & 8) ? sn[0] : c[0]) * ((h & 4) ? sn[1] : c[1])
                       * ((h & 2) ? sn[2] : c[2]) * ((h & 1) ? sn[3] : c[3]);
#pragma unroll
            for (int v = 0; v < 16; v++)
                L16[v] = ((v & 8) ? sn[4] : c[4]) * ((v & 4) ? sn[5] : c[5])
                       * ((v & 2) ? sn[6] : c[6]) * ((v & 1) ? sn[7] : c[7]);
            __half* mrow = m_sm + t * STRIDE;
#pragma unroll
            for (int kk = 0; kk < 256; kk += 8) {
                const float hh = H16[kk >> 4];
                __half tmp[8];
#pragma unroll
                for (int e = 0; e < 8; e += 2) {
                    const __half2 h2 = __floats2half2_rn(hh * L16[(kk + e) & 15],
                                                         hh * L16[(kk + e + 1) & 15]);
                    *(__half2*)&tmp[e] = h2;
                }
                *(uint4*)(mrow + kk) = *(uint4*)tmp;
            }
        }
        if (first) { asm volatile("cp.async.wait_group 0;" ::: "memory"); first = false; }
        __syncthreads();

        // ---- K=128 (per warp) mma loop, register double-buffered ----
        float4 acc[4][8];
#pragma unroll
        for (int ms = 0; ms < 4; ms++)
#pragma unroll
            for (int nt = 0; nt < 8; nt++)
                acc[ms][nt] = make_float4(0.f, 0.f, 0.f, 0.f);

        uint32_t aF[2][4][4], bF[2][4][4];
#pragma unroll
        for (int ms = 0; ms < 4; ms++)
            ldsm4(aF[0][ms], m_u + (uint32_t)(rowA_off + ms * 16 * STRIDE) * 2u);
#pragma unroll
        for (int j = 0; j < 4; j++)
            ldsm4(bF[0][j], b_u + (uint32_t)(rowB_off + j * 16 * STRIDE) * 2u);

#pragma unroll
        for (int it = 0; it < 8; it++) {
            const int p = it & 1;
            if (it < 7) {
                const int kb = (it + 1) * 16;
#pragma unroll
                for (int ms = 0; ms < 4; ms++)
                    ldsm4(aF[p ^ 1][ms],
                          m_u + (uint32_t)(rowA_off + ms * 16 * STRIDE + kb) * 2u);
#pragma unroll
                for (int j = 0; j < 4; j++)
                    ldsm4(bF[p ^ 1][j],
                          b_u + (uint32_t)(rowB_off + j * 16 * STRIDE + kb) * 2u);
            }
#pragma unroll
            for (int ms = 0; ms < 4; ms++) {
#pragma unroll
                for (int j = 0; j < 4; j++) {
                    mma16816(acc[ms][2 * j],     aF[p][ms], bF[p][j][0], bF[p][j][1]);
                    mma16816(acc[ms][2 * j + 1], aF[p][ms], bF[p][j][2], bF[p][j][3]);
                }
            }
        }

        // ---- K-partial exchange: warp (mh,kh) stores ms-pair (1-kh),
        //      keeps pair kh; partner's store lands in region[mh][kh] ----
        __syncthreads();              // all A/B smem reads done
        {
            const int wbase = (mh * 2 + (1 - kh)) * (16 * 32);
#pragma unroll
            for (int i = 0; i < 16; i++) {
                const int ms = 2 * (1 - kh) + (i >> 3), nt = i & 7;
                exch[wbase + i * 32 + lane] = acc[ms][nt];
            }
        }
        __syncthreads();
        {
            const int rbase = (mh * 2 + kh) * (16 * 32);
#pragma unroll
            for (int i = 0; i < 16; i++) {
                const int ms = 2 * kh + (i >> 3), nt = i & 7;
                const float4 v = exch[rbase + i * 32 + lane];
                acc[ms][nt].x += v.x; acc[ms][nt].y += v.y;
                acc[ms][nt].z += v.z; acc[ms][nt].w += v.w;
            }
        }

        // ---- epilogue: T/S partial sums on owned ms pair ----
#pragma unroll
        for (int msl = 0; msl < 2; msl++) {
            const int ms = 2 * kh + msl;
            float Tlo = 0.f, S2lo = 0.f, S1lo = 0.f, S0lo = 0.f;
            float Thi = 0.f, S2hi = 0.f, S1hi = 0.f, S0hi = 0.f;
#pragma unroll
            for (int nt = 0; nt < 8; nt++) {
                const float4 cc = acc[ms][nt];
                const float plo = cc.x * cc.x + cc.y * cc.y;
                const float phi = cc.z * cc.z + cc.w * cc.w;
                Tlo += plo; Thi += phi;
                if (nt & 4) { S2lo += plo; S2hi += phi; }
                if (nt & 2) { S1lo += plo; S1hi += phi; }
                if (nt & 1) { S0lo += plo; S0hi += phi; }
            }
            float T6lo = (tig & 2) ? -Tlo : Tlo;
            float T7lo = (tig & 1) ? -Tlo : Tlo;
            float T6hi = (tig & 2) ? -Thi : Thi;
            float T7hi = (tig & 1) ? -Thi : Thi;

            const float rT  = red4(Tlo),  rT_h = red4(Thi);
            const float rS2 = red4(S2lo), rS2h = red4(S2hi);
            const float rS1 = red4(S1lo), rS1h = red4(S1hi);
            const float rS0 = red4(S0lo), rS0h = red4(S0hi);
            const float rT6 = red4(T6lo), rT6h = red4(T6hi);
            const float rT7 = red4(T7lo), rT7h = red4(T7hi);

            if (tig == 0) {
                const int rlo = mh * 64 + ms * 16 + gid;
                float* plo = comb + rlo * 8;
                plo[0] = s0 * rT;  plo[1] = s1 * rT;  plo[2] = s2 * rT;
                plo[3] = rT - 2.f * rS2;
                plo[4] = rT - 2.f * rS1;
                plo[5] = rT - 2.f * rS0;
                plo[6] = rT6;      plo[7] = rT7;
                float* phi = comb + (rlo + 8) * 8;
                phi[0] = s0 * rT_h; phi[1] = s1 * rT_h; phi[2] = s2 * rT_h;
                phi[3] = rT_h - 2.f * rS2h;
                phi[4] = rT_h - 2.f * rS1h;
                phi[5] = rT_h - 2.f * rS0h;
                phi[6] = rT6h;      phi[7] = rT7h;
            }
        }
        __syncthreads();

        // ---- global atomicAdd (8 eighths converge) ----
        {
            const float* cp2 = comb + t * 8;
            float* op = out + (size_t)(tile * TILE_M + t) * NQ;
#pragma unroll
            for (int q = 0; q < 8; q++)
                atomicAdd(op + q, cp2[q]);
        }
    }
}

// ---------------------------------------------------------------------------
extern "C" void kernel_launch(void* const* d_in, const int* in_sizes, int n_in,
                              void* d_out, int out_size) {
    const float* x = (const float*)d_in[0];
    const float* w = (const float*)d_in[1];
    if (n_in >= 2 && in_sizes[0] < in_sizes[1]) {
        const float* tmp = x; x = w; w = tmp;
    }
    float* out = (float*)d_out;

    cudaFuncSetAttribute(qsim_main_kernel,
                         cudaFuncAttributeMaxDynamicSharedMemorySize, SMEM_TOTAL);

    build_V_kernel<<<544, 256>>>(w, (float4*)out);
    qsim_main_kernel<<<8 * NPER, THREADS, SMEM_TOTAL>>>(x, out);
}

// round 12
// speedup vs baseline: 3.1314x; 3.1314x over previous
#include <cuda_runtime.h>
#include <cuda_fp16.h>
#include <cstdint>

#define NQ 8
#define DIM 256
#define BATCH 65536
#define NL 8

#define THREADS 128
#define TILE_M 64
#define NTILES (BATCH / TILE_M)     // 1024
#define NPER 55                     // CTAs per N-eighth; grid = 440 (3/SM)
#define STRIDE 264                  // smem row stride in halves (256 + 8 pad)

#define M_BYTES (TILE_M * STRIDE * 2)   // 33792
#define B_OFF   M_BYTES
#define B_BYTES (64 * STRIDE * 2)       // 33792
#define SMEM_TOTAL (M_BYTES + B_BYTES)  // 67584  -> 3 CTAs/SM

#define COMB_OFF 0                  // float[64][8] = 2 KB (overlay on m)
#define EXCH_OFF 2048               // float4[4][8][32] = 16 KB (overlay on m)

__device__ __align__(16) __half g_Vn2k[512 * 256];   // [n2][k] GEMM B layout

// ---------------------------------------------------------------------------
// Kernel 1: blocks 0..31 = warp-level entangler simulation (one warp = one
// basis column k). Blocks 32..543 zero out[].
// ---------------------------------------------------------------------------
__global__ void build_V_kernel(const float* __restrict__ w, float4* __restrict__ out4) {
    if (blockIdx.x >= 32) {
        out4[(blockIdx.x - 32) * 256 + threadIdx.x] = make_float4(0.f, 0.f, 0.f, 0.f);
        return;
    }
    __shared__ __half tr[8][528];        // [k within block][n2]
    const int t = threadIdx.x;
    const int warp = t >> 5, lane = t & 31;
    const int k = blockIdx.x * 8 + warp;

    float2 a[8];
#pragma unroll
    for (int r = 0; r < 8; r++) {
        const int idx = lane * 8 + r;
        a[r] = make_float2(idx == k ? 1.f : 0.f, 0.f);
    }

    for (int l = 0; l < NL; l++) {
#pragma unroll
        for (int q = 0; q < 8; q++) {
            float s, c, zs, zc;
            __sincosf(0.5f * w[(l * 8 + q) * 2 + 0], &s, &c);
            __sincosf(0.5f * w[(l * 8 + q) * 2 + 1], &zs, &zc);
            const int p = 7 - q;
            if (p < 3) {
                const int bit = 1 << p;
#pragma unroll
                for (int r = 0; r < 8; r++) {
                    if (!(r & bit)) {
                        const float2 a0 = a[r], a1 = a[r | bit];
                        const float xr0 = c * a0.x - s * a1.x;
                        const float xi0 = c * a0.y - s * a1.y;
                        const float xr1 = s * a0.x + c * a1.x;
                        const float xi1 = s * a0.y + c * a1.y;
                        a[r]       = make_float2(zc * xr0 + zs * xi0, zc * xi0 - zs * xr0);
                        a[r | bit] = make_float2(zc * xr1 - zs * xi1, zc * xi1 + zs * xr1);
                    }
                }
            } else {
                const int lm = 1 << (p - 3);
                const bool hi = (lane & lm) != 0;
                const float zss = hi ? -zs : zs;
#pragma unroll
                for (int r = 0; r < 8; r++) {
                    const float ox = __shfl_xor_sync(0xffffffffu, a[r].x, lm);
                    const float oy = __shfl_xor_sync(0xffffffffu, a[r].y, lm);
                    const float xr = hi ? (s * ox + c * a[r].x) : (c * a[r].x - s * ox);
                    const float xi = hi ? (s * oy + c * a[r].y) : (c * a[r].y - s * oy);
                    a[r] = make_float2(zc * xr + zss * xi, zc * xi - zss * xr);
                }
            }
        }
#pragma unroll
        for (int q = 0; q < 8; q++) {
            const int cp = 7 - q, tp = 7 - ((q + 1) & 7);
            if (cp >= 3 && tp >= 3) {
                const int cl = 1 << (cp - 3), tl = 1 << (tp - 3);
#pragma unroll
                for (int r = 0; r < 8; r++) {
                    const float ox = __shfl_xor_sync(0xffffffffu, a[r].x, tl);
                    const float oy = __shfl_xor_sync(0xffffffffu, a[r].y, tl);
                    if (lane & cl) { a[r].x = ox; a[r].y = oy; }
                }
            } else if (cp >= 3) {
                const int cl = 1 << (cp - 3), tb = 1 << tp;
                if (lane & cl) {
#pragma unroll
                    for (int r = 0; r < 8; r++) {
                        if (!(r & tb)) {
                            const float2 tmp = a[r]; a[r] = a[r | tb]; a[r | tb] = tmp;
                        }
                    }
                }
            } else if (tp >= 3) {
                const int cb = 1 << cp, tl = 1 << (tp - 3);
#pragma unroll
                for (int r = 0; r < 8; r++) {
                    const float ox = __shfl_xor_sync(0xffffffffu, a[r].x, tl);
                    const float oy = __shfl_xor_sync(0xffffffffu, a[r].y, tl);
                    if (r & cb) { a[r].x = ox; a[r].y = oy; }
                }
            } else {
                const int cb = 1 << cp, tb = 1 << tp;
#pragma unroll
                for (int r = 0; r < 8; r++) {
                    if ((r & cb) && !(r & tb)) {
                        const float2 tmp = a[r]; a[r] = a[r | tb]; a[r | tb] = tmp;
                    }
                }
            }
        }
    }

    const int pc = __popc(k) & 3;
#pragma unroll
    for (int r = 0; r < 8; r++) {
        const float2 u = a[r];
        float2 vv;
        if      (pc == 0) vv = u;
        else if (pc == 1) vv = make_float2( u.y, -u.x);
        else if (pc == 2) vv = make_float2(-u.x, -u.y);
        else              vv = make_float2(-u.y,  u.x);
        const int n2 = (lane * 8 + r) * 2;
        *(__half2*)&tr[warp][n2] = __floats2half2_rn(vv.x, vv.y);
    }
    __syncthreads();

    const int kb = blockIdx.x * 8;
#pragma unroll
    for (int i = 0; i < 2; i++) {
        const int n2 = 2 * t + i;
        __half tmp[8];
#pragma unroll
        for (int kk = 0; kk < 8; kk++) tmp[kk] = tr[kk][n2];
        *(uint4*)&g_Vn2k[n2 * 256 + kb] = *(uint4*)tmp;
    }
}

// ---------------------------------------------------------------------------
// helpers
// ---------------------------------------------------------------------------
__device__ __forceinline__ uint32_t smem_u32(const void* p) {
    return (uint32_t)__cvta_generic_to_shared(p);
}
__device__ __forceinline__ void cp_async16(uint32_t dst, const void* src) {
    asm volatile("cp.async.cg.shared.global [%0], [%1], 16;" :: "r"(dst), "l"(src));
}
__device__ __forceinline__ void ldsm4(uint32_t r[4], uint32_t addr) {
    asm volatile("ldmatrix.sync.aligned.m8n8.x4.shared.b16 {%0,%1,%2,%3}, [%4];"
                 : "=r"(r[0]), "=r"(r[1]), "=r"(r[2]), "=r"(r[3]) : "r"(addr));
}
__device__ __forceinline__ void mma16816(float4& c, const uint32_t a[4],
                                         uint32_t b0, uint32_t b1) {
    asm volatile(
        "mma.sync.aligned.m16n8k16.row.col.f32.f16.f16.f32 "
        "{%0,%1,%2,%3}, {%4,%5,%6,%7}, {%8,%9}, {%0,%1,%2,%3};"
        : "+f"(c.x), "+f"(c.y), "+f"(c.z), "+f"(c.w)
        : "r"(a[0]), "r"(a[1]), "r"(a[2]), "r"(a[3]), "r"(b0), "r"(b1));
}
__device__ __forceinline__ float red4(float v) {
    v += __shfl_xor_sync(0xffffffffu, v, 1);
    v += __shfl_xor_sync(0xffffffffu, v, 2);
    return v;
}

// ---------------------------------------------------------------------------
// Kernel 2: persistent GEMM, 3 CTAs/SM, K-split warps.
// CTA = 128 threads (4 warps = (mh, kh)), owns one N-eighth (64 n2 rows).
// Sample tile = 64. Warp tile 32 samples x 64 n2 x K=128.
// K-partials exchanged through smem before squaring; each warp epilogues
// its 16-sample ms = kh group.
// ---------------------------------------------------------------------------
__global__ __launch_bounds__(THREADS, 3)
void qsim_main_kernel(const float* __restrict__ x, float* __restrict__ out) {
    extern __shared__ __align__(16) char smem[];
    __half* m_sm = (__half*)smem;
    float*  comb = (float*)(smem + COMB_OFF);     // [64][8]
    float4* exch = (float4*)(smem + EXCH_OFF);    // [4 regions][8][32]

    const int t = threadIdx.x;
    const int warp = t >> 5, lane = t & 31;
    const int eighth = blockIdx.x & 7;
    const int idx0 = blockIdx.x >> 3;             // 0..54

    // ---- stage this CTA's B eighth (64 n2-rows x 512B) once ----
    {
        const char* src = (const char*)g_Vn2k + eighth * (64 * 512);
        const uint32_t dst = smem_u32(smem + B_OFF);
#pragma unroll
        for (int i = 0; i < 16; i++) {
            const int e = t + THREADS * i;        // 2048 x 16B
            const int row = e >> 5, c16 = e & 31;
            cp_async16(dst + row * (STRIDE * 2) + c16 * 16,
                       src + row * 512 + c16 * 16);
        }
        asm volatile("cp.async.commit_group;" ::: "memory");
    }

    const uint32_t m_u = smem_u32(m_sm);
    const uint32_t b_u = smem_u32(smem + B_OFF);

    const int mh = warp >> 1;         // 32-sample half of the tile
    const int kh = warp & 1;          // K half (128 each)
    const int gid = lane >> 2, tig = lane & 3;

    const int rowA_off = (mh * 32 + (lane & 7) + 8 * ((lane >> 3) & 1)) * STRIDE
                       + 8 * (lane >> 4) + kh * 128;
    const int rowB_off = (((lane >> 4) & 1) * 8 + (lane & 7)) * STRIDE
                       + 8 * ((lane >> 3) & 1) + kh * 128;

    // sign constants from eighth (n bits 7:5 -> q0,q1,q2)
    const float s0 = (eighth & 4) ? -1.f : 1.f;
    const float s1 = (eighth & 2) ? -1.f : 1.f;
    const float s2 = (eighth & 1) ? -1.f : 1.f;

    const int s_mine  = t >> 1;       // sample row this thread builds (0..63)
    const int kg_mine = t & 1;        // which 128-k half this thread builds

    bool first = true;
    for (int tile = idx0; tile < NTILES; tile += NPER) {
        // prefetch angles (two threads share one sample row)
        float xv[8];
        {
            const float* xp = x + (size_t)(tile * TILE_M + s_mine) * NQ;
#pragma unroll
            for (int q = 0; q < 8; q++) xv[q] = xp[q];
        }
        __syncthreads();              // prev tile's comb/exch reads done

        // ---- build m tile: thread t -> sample s_mine, k in [kg*128, +128) ----
        {
            float c[8], sn[8];
#pragma unroll
            for (int q = 0; q < 8; q++) {
                float sv, cv;
                __sincosf(0.5f * xv[q], &sv, &cv);
                c[q] = cv; sn[q] = sv;
            }
            float H16[16], L16[16];
#pragma unroll
            for (int h = 0; h < 16; h++)
                H16[h] = ((h & 8) ? sn[0] : c[0]) * ((h & 4) ? sn[1] : c[1])
                       * ((h & 2) ? sn[2] : c[2]) * ((h & 1) ? sn[3] : c[3]);
#pragma unroll
            for (int v = 0; v < 16; v++)
                L16[v] = ((v & 8) ? sn[4] : c[4]) * ((v & 4) ? sn[5] : c[5])
                       * ((v & 2) ? sn[6] : c[6]) * ((v & 1) ? sn[7] : c[7]);
            __half* mrow = m_sm + s_mine * STRIDE + kg_mine * 128;
            const int kbase = kg_mine * 128;
#pragma unroll
            for (int kk = 0; kk < 128; kk += 8) {
                const float hh = H16[(kbase + kk) >> 4];
                __half tmp[8];
#pragma unroll
                for (int e = 0; e < 8; e += 2) {
                    const __half2 h2 = __floats2half2_rn(hh * L16[(kk + e) & 15],
                                                         hh * L16[(kk + e + 1) & 15]);
                    *(__half2*)&tmp[e] = h2;
                }
                *(uint4*)(mrow + kk) = *(uint4*)tmp;
            }
        }
        if (first) { asm volatile("cp.async.wait_group 0;" ::: "memory"); first = false; }
        __syncthreads();

        // ---- K=128 (per warp) mma loop, register double-buffered ----
        float4 acc[2][8];
#pragma unroll
        for (int ms = 0; ms < 2; ms++)
#pragma unroll
            for (int nt = 0; nt < 8; nt++)
                acc[ms][nt] = make_float4(0.f, 0.f, 0.f, 0.f);

        uint32_t aF[2][2][4], bF[2][4][4];
#pragma unroll
        for (int ms = 0; ms < 2; ms++)
            ldsm4(aF[0][ms], m_u + (uint32_t)(rowA_off + ms * 16 * STRIDE) * 2u);
#pragma unroll
        for (int j = 0; j < 4; j++)
            ldsm4(bF[0][j], b_u + (uint32_t)(rowB_off + j * 16 * STRIDE) * 2u);

#pragma unroll
        for (int it = 0; it < 8; it++) {
            const int p = it & 1;
            if (it < 7) {
                const int kb = (it + 1) * 16;
#pragma unroll
                for (int ms = 0; ms < 2; ms++)
                    ldsm4(aF[p ^ 1][ms],
                          m_u + (uint32_t)(rowA_off + ms * 16 * STRIDE + kb) * 2u);
#pragma unroll
                for (int j = 0; j < 4; j++)
                    ldsm4(bF[p ^ 1][j],
                          b_u + (uint32_t)(rowB_off + j * 16 * STRIDE + kb) * 2u);
            }
#pragma unroll
            for (int ms = 0; ms < 2; ms++) {
#pragma unroll
                for (int j = 0; j < 4; j++) {
                    mma16816(acc[ms][2 * j],     aF[p][ms], bF[p][j][0], bF[p][j][1]);
                    mma16816(acc[ms][2 * j + 1], aF[p][ms], bF[p][j][2], bF[p][j][3]);
                }
            }
        }

        // ---- K-partial exchange: warp (mh,kh) keeps ms=kh, stores ms=1-kh
        //      to region[mh*2+(1-kh)]; partner's store read from [mh*2+kh] ----
        __syncthreads();              // all A/B smem reads done
        {
            const int wbase = (mh * 2 + (1 - kh)) * (8 * 32);
#pragma unroll
            for (int nt = 0; nt < 8; nt++)
                exch[wbase + nt * 32 + lane] = acc[1 - kh][nt];
        }
        __syncthreads();
        {
            const int rbase = (mh * 2 + kh) * (8 * 32);
#pragma unroll
            for (int nt = 0; nt < 8; nt++) {
                const float4 v = exch[rbase + nt * 32 + lane];
                acc[kh][nt].x += v.x; acc[kh][nt].y += v.y;
                acc[kh][nt].z += v.z; acc[kh][nt].w += v.w;
            }
        }

        // ---- epilogue: T/S partial sums on owned ms = kh ----
        {
            float Tlo = 0.f, S2lo = 0.f, S1lo = 0.f, S0lo = 0.f;
            float Thi = 0.f, S2hi = 0.f, S1hi = 0.f, S0hi = 0.f;
#pragma unroll
            for (int nt = 0; nt < 8; nt++) {
                const float4 cc = acc[kh][nt];
                const float plo = cc.x * cc.x + cc.y * cc.y;
                const float phi = cc.z * cc.z + cc.w * cc.w;
                Tlo += plo; Thi += phi;
                if (nt & 4) { S2lo += plo; S2hi += phi; }
                if (nt & 2) { S1lo += plo; S1hi += phi; }
                if (nt & 1) { S0lo += plo; S0hi += phi; }
            }
            float T6lo = (tig & 2) ? -Tlo : Tlo;
            float T7lo = (tig & 1) ? -Tlo : Tlo;
            float T6hi = (tig & 2) ? -Thi : Thi;
            float T7hi = (tig & 1) ? -Thi : Thi;

            const float rT  = red4(Tlo),  rT_h = red4(Thi);
            const float rS2 = red4(S2lo), rS2h = red4(S2hi);
            const float rS1 = red4(S1lo), rS1h = red4(S1hi);
            const float rS0 = red4(S0lo), rS0h = red4(S0hi);
            const float rT6 = red4(T6lo), rT6h = red4(T6hi);
            const float rT7 = red4(T7lo), rT7h = red4(T7hi);

            if (tig == 0) {
                const int rlo = mh * 32 + kh * 16 + gid;
                float* plo = comb + rlo * 8;
                plo[0] = s0 * rT;  plo[1] = s1 * rT;  plo[2] = s2 * rT;
                plo[3] = rT - 2.f * rS2;
                plo[4] = rT - 2.f * rS1;
                plo[5] = rT - 2.f * rS0;
                plo[6] = rT6;      plo[7] = rT7;
                float* phi = comb + (rlo + 8) * 8;
                phi[0] = s0 * rT_h; phi[1] = s1 * rT_h; phi[2] = s2 * rT_h;
                phi[3] = rT_h - 2.f * rS2h;
                phi[4] = rT_h - 2.f * rS1h;
                phi[5] = rT_h - 2.f * rS0h;
                phi[6] = rT6h;      phi[7] = rT7h;
            }
        }
        __syncthreads();

        // ---- global atomicAdd (8 eighths converge); 4 per thread ----
        {
            const int rr = t >> 1, qp = (t & 1) * 4;
            const float* cp2 = comb + rr * 8 + qp;
            float* op = out + (size_t)(tile * TILE_M + rr) * NQ + qp;
            atomicAdd(op,     cp2[0]);
            atomicAdd(op + 1, cp2[1]);
            atomicAdd(op + 2, cp2[2]);
            atomicAdd(op + 3, cp2[3]);
        }
    }
}

// ---------------------------------------------------------------------------
extern "C" void kernel_launch(void* const* d_in, const int* in_sizes, int n_in,
                              void* d_out, int out_size) {
    const float* x = (const float*)d_in[0];
    const float* w = (const float*)d_in[1];
    if (n_in >= 2 && in_sizes[0] < in_sizes[1]) {
        const float* tmp = x; x = w; w = tmp;
    }
    float* out = (float*)d_out;

    cudaFuncSetAttribute(qsim_main_kernel,
                         cudaFuncAttributeMaxDynamicSharedMemorySize, SMEM_TOTAL);

    build_V_kernel<<<544, 256>>>(w, (float4*)out);
    qsim_main_kernel<<<8 * NPER, THREADS, SMEM_TOTAL>>>(x, out);
}

// round 14
// speedup vs baseline: 5.2276x; 1.6694x over previous
#include <cuda_runtime.h>
#include <cuda_fp16.h>
#include <cstdint>

#define NQ 8
#define DIM 256
#define BATCH 65536
#define NL 8

#define THREADS 128
#define TILE_M 128
#define NTILES (BATCH / TILE_M)     // 512
#define NPERQ 37                    // CTAs per N-quarter; grid = 148 (1/SM)
#define STRIDE 264                  // smem row stride in halves (256 + 8 pad)

#define M_BYTES (TILE_M * STRIDE * 2)   // 67584
#define B_OFF   M_BYTES
#define B_BYTES (128 * STRIDE * 2)      // 67584
#define SMEM_TOTAL (M_BYTES + B_BYTES)  // 135168 -> 1 CTA/SM

__device__ __align__(16) __half g_Vn2k[512 * 256];   // [n2][k] GEMM B layout

// ---------------------------------------------------------------------------
// Kernel 1: blocks 0..31 = warp-level entangler simulation (one warp = one
// basis column k). Blocks 32..543 zero out[].
// ---------------------------------------------------------------------------
__global__ void build_V_kernel(const float* __restrict__ w, float4* __restrict__ out4) {
    if (blockIdx.x >= 32) {
        out4[(blockIdx.x - 32) * 256 + threadIdx.x] = make_float4(0.f, 0.f, 0.f, 0.f);
        return;
    }
    __shared__ __half tr[8][528];        // [k within block][n2]
    const int t = threadIdx.x;
    const int warp = t >> 5, lane = t & 31;
    const int k = blockIdx.x * 8 + warp;

    float2 a[8];
#pragma unroll
    for (int r = 0; r < 8; r++) {
        const int idx = lane * 8 + r;
        a[r] = make_float2(idx == k ? 1.f : 0.f, 0.f);
    }

    for (int l = 0; l < NL; l++) {
#pragma unroll
        for (int q = 0; q < 8; q++) {
            float s, c, zs, zc;
            __sincosf(0.5f * w[(l * 8 + q) * 2 + 0], &s, &c);
            __sincosf(0.5f * w[(l * 8 + q) * 2 + 1], &zs, &zc);
            const int p = 7 - q;
            if (p < 3) {
                const int bit = 1 << p;
#pragma unroll
                for (int r = 0; r < 8; r++) {
                    if (!(r & bit)) {
                        const float2 a0 = a[r], a1 = a[r | bit];
                        const float xr0 = c * a0.x - s * a1.x;
                        const float xi0 = c * a0.y - s * a1.y;
                        const float xr1 = s * a0.x + c * a1.x;
                        const float xi1 = s * a0.y + c * a1.y;
                        a[r]       = make_float2(zc * xr0 + zs * xi0, zc * xi0 - zs * xr0);
                        a[r | bit] = make_float2(zc * xr1 - zs * xi1, zc * xi1 + zs * xr1);
                    }
                }
            } else {
                const int lm = 1 << (p - 3);
                const bool hi = (lane & lm) != 0;
                const float zss = hi ? -zs : zs;
#pragma unroll
                for (int r = 0; r < 8; r++) {
                    const float ox = __shfl_xor_sync(0xffffffffu, a[r].x, lm);
                    const float oy = __shfl_xor_sync(0xffffffffu, a[r].y, lm);
                    const float xr = hi ? (s * ox + c * a[r].x) : (c * a[r].x - s * ox);
                    const float xi = hi ? (s * oy + c * a[r].y) : (c * a[r].y - s * oy);
                    a[r] = make_float2(zc * xr + zss * xi, zc * xi - zss * xr);
                }
            }
        }
#pragma unroll
        for (int q = 0; q < 8; q++) {
            const int cp = 7 - q, tp = 7 - ((q + 1) & 7);
            if (cp >= 3 && tp >= 3) {
                const int cl = 1 << (cp - 3), tl = 1 << (tp - 3);
#pragma unroll
                for (int r = 0; r < 8; r++) {
                    const float ox = __shfl_xor_sync(0xffffffffu, a[r].x, tl);
                    const float oy = __shfl_xor_sync(0xffffffffu, a[r].y, tl);
                    if (lane & cl) { a[r].x = ox; a[r].y = oy; }
                }
            } else if (cp >= 3) {
                const int cl = 1 << (cp - 3), tb = 1 << tp;
                if (lane & cl) {
#pragma unroll
                    for (int r = 0; r < 8; r++) {
                        if (!(r & tb)) {
                            const float2 tmp = a[r]; a[r] = a[r | tb]; a[r | tb] = tmp;
                        }
                    }
                }
            } else if (tp >= 3) {
                const int cb = 1 << cp, tl = 1 << (tp - 3);
#pragma unroll
                for (int r = 0; r < 8; r++) {
                    const float ox = __shfl_xor_sync(0xffffffffu, a[r].x, tl);
                    const float oy = __shfl_xor_sync(0xffffffffu, a[r].y, tl);
                    if (r & cb) { a[r].x = ox; a[r].y = oy; }
                }
            } else {
                const int cb = 1 << cp, tb = 1 << tp;
#pragma unroll
                for (int r = 0; r < 8; r++) {
                    if ((r & cb) && !(r & tb)) {
                        const float2 tmp = a[r]; a[r] = a[r | tb]; a[r | tb] = tmp;
                    }
                }
            }
        }
    }

    const int pc = __popc(k) & 3;
#pragma unroll
    for (int r = 0; r < 8; r++) {
        const float2 u = a[r];
        float2 vv;
        if      (pc == 0) vv = u;
        else if (pc == 1) vv = make_float2( u.y, -u.x);
        else if (pc == 2) vv = make_float2(-u.x, -u.y);
        else              vv = make_float2(-u.y,  u.x);
        const int n2 = (lane * 8 + r) * 2;
        *(__half2*)&tr[warp][n2] = __floats2half2_rn(vv.x, vv.y);
    }
    __syncthreads();

    const int kb = blockIdx.x * 8;
#pragma unroll
    for (int i = 0; i < 2; i++) {
        const int n2 = 2 * t + i;
        __half tmp[8];
#pragma unroll
        for (int kk = 0; kk < 8; kk++) tmp[kk] = tr[kk][n2];
        *(uint4*)&g_Vn2k[n2 * 256 + kb] = *(uint4*)tmp;
    }
}

// ---------------------------------------------------------------------------
// helpers
// ---------------------------------------------------------------------------
__device__ __forceinline__ uint32_t smem_u32(const void* p) {
    return (uint32_t)__cvta_generic_to_shared(p);
}
__device__ __forceinline__ void cp_async16(uint32_t dst, const void* src) {
    asm volatile("cp.async.cg.shared.global [%0], [%1], 16;" :: "r"(dst), "l"(src));
}
__device__ __forceinline__ void ldsm4(uint32_t r[4], uint32_t addr) {
    asm volatile("ldmatrix.sync.aligned.m8n8.x4.shared.b16 {%0,%1,%2,%3}, [%4];"
                 : "=r"(r[0]), "=r"(r[1]), "=r"(r[2]), "=r"(r[3]) : "r"(addr));
}
__device__ __forceinline__ void mma16816(float4& c, const uint32_t a[4],
                                         uint32_t b0, uint32_t b1) {
    asm volatile(
        "mma.sync.aligned.m16n8k16.row.col.f32.f16.f16.f32 "
        "{%0,%1,%2,%3}, {%4,%5,%6,%7}, {%8,%9}, {%0,%1,%2,%3};"
        : "+f"(c.x), "+f"(c.y), "+f"(c.z), "+f"(c.w)
        : "r"(a[0]), "r"(a[1]), "r"(a[2]), "r"(a[3]), "r"(b0), "r"(b1));
}
__device__ __forceinline__ float red4(float v) {
    v += __shfl_xor_sync(0xffffffffu, v, 1);
    v += __shfl_xor_sync(0xffffffffu, v, 2);
    return v;
}

// ---------------------------------------------------------------------------
// Kernel 2: persistent GEMM, 1 CTA/SM, warp tile 64 samples x 64 n2
// (LDSM ratio 0.031). CTA = 128 threads (4 warps = mh2 x nq2), TILE_M=128,
// owns one N-quarter (128 n2 rows resident). Single-buffered fragments.
// comb is [2 nq][128 rows][8 q] — the nq dimension was the round-13 bug.
// ---------------------------------------------------------------------------
__global__ __launch_bounds__(THREADS, 1)
void qsim_main_kernel(const float* __restrict__ x, float* __restrict__ out) {
    extern __shared__ __align__(16) char smem[];
    __half* m_sm = (__half*)smem;
    float*  comb = (float*)smem;            // overlay: [2][128][8] floats = 8 KB

    const int t = threadIdx.x;
    const int warp = t >> 5, lane = t & 31;
    const int quarter = blockIdx.x & 3;
    const int idx0 = blockIdx.x >> 2;       // 0..36

    // ---- stage this CTA's B quarter (128 n2-rows x 512B) once ----
    {
        const char* src = (const char*)g_Vn2k + quarter * (128 * 512);
        const uint32_t dst = smem_u32(smem + B_OFF);
#pragma unroll
        for (int i = 0; i < 32; i++) {
            const int e = t + THREADS * i;          // 4096 x 16B
            const int row = e >> 5, c16 = e & 31;
            cp_async16(dst + row * (STRIDE * 2) + c16 * 16,
                       src + row * 512 + c16 * 16);
        }
        asm volatile("cp.async.commit_group;" ::: "memory");
    }

    const uint32_t m_u = smem_u32(m_sm);
    const uint32_t b_u = smem_u32(smem + B_OFF);

    const int mh = warp >> 1;         // 64-sample half of the tile
    const int nq = warp & 1;          // 64-n2 chunk (32 amplitudes)
    const int gid = lane >> 2, tig = lane & 3;

    const int rowA_off = (mh * 64 + (lane & 7) + 8 * ((lane >> 3) & 1)) * STRIDE
                       + 8 * (lane >> 4);
    const int rowB_off = (nq * 64 + ((lane >> 4) & 1) * 8 + (lane & 7)) * STRIDE
                       + 8 * ((lane >> 3) & 1);

    // sign constants (n bits 7:6 from quarter -> q0,q1; bit5 from nq -> q2)
    const float s0 = (quarter & 2) ? -1.f : 1.f;
    const float s1 = (quarter & 1) ? -1.f : 1.f;
    const float s2 = nq ? -1.f : 1.f;

    bool first = true;
    for (int tile = idx0; tile < NTILES; tile += NPERQ) {
        // prefetch angles (thread t = sample t of the tile)
        float xv[8];
        {
            const float* xp = x + (size_t)(tile * TILE_M + t) * NQ;
#pragma unroll
            for (int q = 0; q < 8; q++) xv[q] = xp[q];
        }
        __syncthreads();              // prev tile's comb reads done

        // ---- build m tile: thread t -> sample t, all 256 k ----
        {
            float c[8], sn[8];
#pragma unroll
            for (int q = 0; q < 8; q++) {
                float sv, cv;
                __sincosf(0.5f * xv[q], &sv, &cv);
                c[q] = cv; sn[q] = sv;
            }
            float H16[16], L16[16];
#pragma unroll
            for (int h = 0; h < 16; h++)
                H16[h] = ((h & 8) ? sn[0] : c[0]) * ((h & 4) ? sn[1] : c[1])
                       * ((h & 2) ? sn[2] : c[2]) * ((h & 1) ? sn[3] : c[3]);
#pragma unroll
            for (int v = 0; v < 16; v++)
                L16[v] = ((v & 8) ? sn[4] : c[4]) * ((v & 4) ? sn[5] : c[5])
                       * ((v & 2) ? sn[6] : c[6]) * ((v & 1) ? sn[7] : c[7]);
            __half* mrow = m_sm + t * STRIDE;
#pragma unroll
            for (int kk = 0; kk < 256; kk += 8) {
                const float hh = H16[kk >> 4];
                __half tmp[8];
#pragma unroll
                for (int e = 0; e < 8; e += 2) {
                    const __half2 h2 = __floats2half2_rn(hh * L16[(kk + e) & 15],
                                                         hh * L16[(kk + e + 1) & 15]);
                    *(__half2*)&tmp[e] = h2;
                }
                *(uint4*)(mrow + kk) = *(uint4*)tmp;
            }
        }
        if (first) { asm volatile("cp.async.wait_group 0;" ::: "memory"); first = false; }
        __syncthreads();

        // ---- K=256 mma loop, single-buffered fragments (register budget) ----
        float4 acc[4][8];
#pragma unroll
        for (int ms = 0; ms < 4; ms++)
#pragma unroll
            for (int nt = 0; nt < 8; nt++)
                acc[ms][nt] = make_float4(0.f, 0.f, 0.f, 0.f);

#pragma unroll
        for (int it = 0; it < 16; it++) {
            const int kb = it * 16;
            uint32_t aF[4][4], bF[4][4];
#pragma unroll
            for (int ms = 0; ms < 4; ms++)
                ldsm4(aF[ms], m_u + (uint32_t)(rowA_off + ms * 16 * STRIDE + kb) * 2u);
#pragma unroll
            for (int j = 0; j < 4; j++)
                ldsm4(bF[j], b_u + (uint32_t)(rowB_off + j * 16 * STRIDE + kb) * 2u);
#pragma unroll
            for (int ms = 0; ms < 4; ms++) {
#pragma unroll
                for (int j = 0; j < 4; j++) {
                    mma16816(acc[ms][2 * j],     aF[ms], bF[j][0], bF[j][1]);
                    mma16816(acc[ms][2 * j + 1], aF[ms], bF[j][2], bF[j][3]);
                }
            }
        }

        // ---- epilogue: T/S partial sums per ms; comb[nq][row][q] ----
        __syncthreads();              // all warps done reading m_sm (comb overlay)
#pragma unroll
        for (int ms = 0; ms < 4; ms++) {
            float Tlo = 0.f, S2lo = 0.f, S1lo = 0.f, S0lo = 0.f;
            float Thi = 0.f, S2hi = 0.f, S1hi = 0.f, S0hi = 0.f;
#pragma unroll
            for (int nt = 0; nt < 8; nt++) {
                const float4 cc = acc[ms][nt];
                const float plo = cc.x * cc.x + cc.y * cc.y;
                const float phi = cc.z * cc.z + cc.w * cc.w;
                Tlo += plo; Thi += phi;
                if (nt & 4) { S2lo += plo; S2hi += phi; }
                if (nt & 2) { S1lo += plo; S1hi += phi; }
                if (nt & 1) { S0lo += plo; S0hi += phi; }
            }
            float T6lo = (tig & 2) ? -Tlo : Tlo;
            float T7lo = (tig & 1) ? -Tlo : Tlo;
            float T6hi = (tig & 2) ? -Thi : Thi;
            float T7hi = (tig & 1) ? -Thi : Thi;

            const float rT  = red4(Tlo),  rT_h = red4(Thi);
            const float rS2 = red4(S2lo), rS2h = red4(S2hi);
            const float rS1 = red4(S1lo), rS1h = red4(S1hi);
            const float rS0 = red4(S0lo), rS0h = red4(S0hi);
            const float rT6 = red4(T6lo), rT6h = red4(T6hi);
            const float rT7 = red4(T7lo), rT7h = red4(T7hi);

            if (tig == 0) {
                const int rlo = mh * 64 + ms * 16 + gid;
                float* plo = comb + (nq * 128 + rlo) * 8;
                plo[0] = s0 * rT;  plo[1] = s1 * rT;  plo[2] = s2 * rT;
                plo[3] = rT - 2.f * rS2;
                plo[4] = rT - 2.f * rS1;
                plo[5] = rT - 2.f * rS0;
                plo[6] = rT6;      plo[7] = rT7;
                float* phi = comb + (nq * 128 + rlo + 8) * 8;
                phi[0] = s0 * rT_h; phi[1] = s1 * rT_h; phi[2] = s2 * rT_h;
                phi[3] = rT_h - 2.f * rS2h;
                phi[4] = rT_h - 2.f * rS1h;
                phi[5] = rT_h - 2.f * rS0h;
                phi[6] = rT6h;      phi[7] = rT7h;
            }
        }
        __syncthreads();

        // ---- merge nq halves; 4 quarters converge in global atomics ----
        {
            const float* c0 = comb + t * 8;
            const float* c1 = comb + (128 + t) * 8;
            float* op = out + (size_t)(tile * TILE_M + t) * NQ;
#pragma unroll
            for (int q = 0; q < 8; q++)
                atomicAdd(op + q, c0[q] + c1[q]);
        }
    }
}

// ---------------------------------------------------------------------------
extern "C" void kernel_launch(void* const* d_in, const int* in_sizes, int n_in,
                              void* d_out, int out_size) {
    const float* x = (const float*)d_in[0];
    const float* w = (const float*)d_in[1];
    if (n_in >= 2 && in_sizes[0] < in_sizes[1]) {
        const float* tmp = x; x = w; w = tmp;
    }
    float* out = (float*)d_out;

    cudaFuncSetAttribute(qsim_main_kernel,
                         cudaFuncAttributeMaxDynamicSharedMemorySize, SMEM_TOTAL);

    build_V_kernel<<<544, 256>>>(w, (float4*)out);
    qsim_main_kernel<<<4 * NPERQ, THREADS, SMEM_TOTAL>>>(x, out);
}

// round 15
// speedup vs baseline: 5.8742x; 1.1237x over previous
#include <cuda_runtime.h>
#include <cuda_fp16.h>
#include <cstdint>

#define NQ 8
#define DIM 256
#define BATCH 65536
#define NL 8

#define THREADS 256
#define TILE_M 128
#define NTILES (BATCH / TILE_M)     // 512
#define NPERH 74                    // CTAs per N-half; grid = 148 (1/SM)
#define STRIDE 264                  // smem row stride in halves (256 + 8 pad)

#define M_BYTES (TILE_M * STRIDE * 2)       // 67584
#define B_OFF   M_BYTES
#define B_BYTES (256 * STRIDE * 2)          // 135168
#define COMB_OFF (B_OFF + B_BYTES)          // 202752
#define COMB_BYTES (4 * 128 * 8 * 4)        // 16384
#define SMEM_TOTAL (COMB_OFF + COMB_BYTES)  // 219136 (<228K, 1 CTA/SM)

__device__ __align__(16) __half g_Vn2k[512 * 256];   // [n2][k] GEMM B layout

// ---------------------------------------------------------------------------
// Kernel 1: blocks 0..31 = warp-level entangler simulation (one warp = one
// basis column k). Blocks 32..543 zero out[].
// ---------------------------------------------------------------------------
__global__ void build_V_kernel(const float* __restrict__ w, float4* __restrict__ out4) {
    if (blockIdx.x >= 32) {
        out4[(blockIdx.x - 32) * 256 + threadIdx.x] = make_float4(0.f, 0.f, 0.f, 0.f);
        return;
    }
    __shared__ __half tr[8][528];        // [k within block][n2]
    const int t = threadIdx.x;
    const int warp = t >> 5, lane = t & 31;
    const int k = blockIdx.x * 8 + warp;

    float2 a[8];
#pragma unroll
    for (int r = 0; r < 8; r++) {
        const int idx = lane * 8 + r;
        a[r] = make_float2(idx == k ? 1.f : 0.f, 0.f);
    }

    for (int l = 0; l < NL; l++) {
#pragma unroll
        for (int q = 0; q < 8; q++) {
            float s, c, zs, zc;
            __sincosf(0.5f * w[(l * 8 + q) * 2 + 0], &s, &c);
            __sincosf(0.5f * w[(l * 8 + q) * 2 + 1], &zs, &zc);
            const int p = 7 - q;
            if (p < 3) {
                const int bit = 1 << p;
#pragma unroll
                for (int r = 0; r < 8; r++) {
                    if (!(r & bit)) {
                        const float2 a0 = a[r], a1 = a[r | bit];
                        const float xr0 = c * a0.x - s * a1.x;
                        const float xi0 = c * a0.y - s * a1.y;
                        const float xr1 = s * a0.x + c * a1.x;
                        const float xi1 = s * a0.y + c * a1.y;
                        a[r]       = make_float2(zc * xr0 + zs * xi0, zc * xi0 - zs * xr0);
                        a[r | bit] = make_float2(zc * xr1 - zs * xi1, zc * xi1 + zs * xr1);
                    }
                }
            } else {
                const int lm = 1 << (p - 3);
                const bool hi = (lane & lm) != 0;
                const float zss = hi ? -zs : zs;
#pragma unroll
                for (int r = 0; r < 8; r++) {
                    const float ox = __shfl_xor_sync(0xffffffffu, a[r].x, lm);
                    const float oy = __shfl_xor_sync(0xffffffffu, a[r].y, lm);
                    const float xr = hi ? (s * ox + c * a[r].x) : (c * a[r].x - s * ox);
                    const float xi = hi ? (s * oy + c * a[r].y) : (c * a[r].y - s * oy);
                    a[r] = make_float2(zc * xr + zss * xi, zc * xi - zss * xr);
                }
            }
        }
#pragma unroll
        for (int q = 0; q < 8; q++) {
            const int cp = 7 - q, tp = 7 - ((q + 1) & 7);
            if (cp >= 3 && tp >= 3) {
                const int cl = 1 << (cp - 3), tl = 1 << (tp - 3);
#pragma unroll
                for (int r = 0; r < 8; r++) {
                    const float ox = __shfl_xor_sync(0xffffffffu, a[r].x, tl);
                    const float oy = __shfl_xor_sync(0xffffffffu, a[r].y, tl);
                    if (lane & cl) { a[r].x = ox; a[r].y = oy; }
                }
            } else if (cp >= 3) {
                const int cl = 1 << (cp - 3), tb = 1 << tp;
                if (lane & cl) {
#pragma unroll
                    for (int r = 0; r < 8; r++) {
                        if (!(r & tb)) {
                            const float2 tmp = a[r]; a[r] = a[r | tb]; a[r | tb] = tmp;
                        }
                    }
                }
            } else if (tp >= 3) {
                const int cb = 1 << cp, tl = 1 << (tp - 3);
#pragma unroll
                for (int r = 0; r < 8; r++) {
                    const float ox = __shfl_xor_sync(0xffffffffu, a[r].x, tl);
                    const float oy = __shfl_xor_sync(0xffffffffu, a[r].y, tl);
                    if (r & cb) { a[r].x = ox; a[r].y = oy; }
                }
            } else {
                const int cb = 1 << cp, tb = 1 << tp;
#pragma unroll
                for (int r = 0; r < 8; r++) {
                    if ((r & cb) && !(r & tb)) {
                        const float2 tmp = a[r]; a[r] = a[r | tb]; a[r | tb] = tmp;
                    }
                }
            }
        }
    }

    const int pc = __popc(k) & 3;
#pragma unroll
    for (int r = 0; r < 8; r++) {
        const float2 u = a[r];
        float2 vv;
        if      (pc == 0) vv = u;
        else if (pc == 1) vv = make_float2( u.y, -u.x);
        else if (pc == 2) vv = make_float2(-u.x, -u.y);
        else              vv = make_float2(-u.y,  u.x);
        const int n2 = (lane * 8 + r) * 2;
        *(__half2*)&tr[warp][n2] = __floats2half2_rn(vv.x, vv.y);
    }
    __syncthreads();

    const int kb = blockIdx.x * 8;
#pragma unroll
    for (int i = 0; i < 2; i++) {
        const int n2 = 2 * t + i;
        __half tmp[8];
#pragma unroll
        for (int kk = 0; kk < 8; kk++) tmp[kk] = tr[kk][n2];
        *(uint4*)&g_Vn2k[n2 * 256 + kb] = *(uint4*)tmp;
    }
}

// ---------------------------------------------------------------------------
// helpers
// ---------------------------------------------------------------------------
__device__ __forceinline__ uint32_t smem_u32(const void* p) {
    return (uint32_t)__cvta_generic_to_shared(p);
}
__device__ __forceinline__ void cp_async16(uint32_t dst, const void* src) {
    asm volatile("cp.async.cg.shared.global [%0], [%1], 16;" :: "r"(dst), "l"(src));
}
__device__ __forceinline__ void ldsm4(uint32_t r[4], uint32_t addr) {
    asm volatile("ldmatrix.sync.aligned.m8n8.x4.shared.b16 {%0,%1,%2,%3}, [%4];"
                 : "=r"(r[0]), "=r"(r[1]), "=r"(r[2]), "=r"(r[3]) : "r"(addr));
}
__device__ __forceinline__ void mma16816(float4& c, const uint32_t a[4],
                                         uint32_t b0, uint32_t b1) {
    asm volatile(
        "mma.sync.aligned.m16n8k16.row.col.f32.f16.f16.f32 "
        "{%0,%1,%2,%3}, {%4,%5,%6,%7}, {%8,%9}, {%0,%1,%2,%3};"
        : "+f"(c.x), "+f"(c.y), "+f"(c.z), "+f"(c.w)
        : "r"(a[0]), "r"(a[1]), "r"(a[2]), "r"(a[3]), "r"(b0), "r"(b1));
}
__device__ __forceinline__ float red4(float v) {
    v += __shfl_xor_sync(0xffffffffu, v, 1);
    v += __shfl_xor_sync(0xffffffffu, v, 2);
    return v;
}

// ---------------------------------------------------------------------------
// Kernel 2: persistent GEMM, 1 CTA/SM, 8 warps (2/SMSP), warp tile
// 64 samples x 64 n2 (LDSM ratio 0.031), TILE_M=128, B-half resident
// (256 n2 rows), double-buffered fragments, cheap T/S epilogue into a
// dedicated comb[4 nq][128][8] region.
// ---------------------------------------------------------------------------
__global__ __launch_bounds__(THREADS, 1)
void qsim_main_kernel(const float* __restrict__ x, float* __restrict__ out) {
    extern __shared__ __align__(16) char smem[];
    __half* m_sm = (__half*)smem;
    float*  comb = (float*)(smem + COMB_OFF);     // [4][128][8]

    const int t = threadIdx.x;
    const int warp = t >> 5, lane = t & 31;
    const int half = blockIdx.x & 1;
    const int idx0 = blockIdx.x >> 1;             // 0..73

    // ---- stage this CTA's B half (256 n2-rows x 512B) once ----
    {
        const char* src = (const char*)g_Vn2k + half * (256 * 512);
        const uint32_t dst = smem_u32(smem + B_OFF);
#pragma unroll
        for (int i = 0; i < 32; i++) {
            const int e = t + THREADS * i;        // 8192 x 16B
            const int row = e >> 5, c16 = e & 31;
            cp_async16(dst + row * (STRIDE * 2) + c16 * 16,
                       src + row * 512 + c16 * 16);
        }
        asm volatile("cp.async.commit_group;" ::: "memory");
    }

    const uint32_t m_u = smem_u32(m_sm);
    const uint32_t b_u = smem_u32(smem + B_OFF);

    const int mh = warp >> 2;         // 64-sample half of the tile
    const int nq = warp & 3;          // 64-n2 chunk (32 amplitudes)
    const int gid = lane >> 2, tig = lane & 3;

    const int rowA_off = (mh * 64 + (lane & 7) + 8 * ((lane >> 3) & 1)) * STRIDE
                       + 8 * (lane >> 4);
    const int rowB_off = (nq * 64 + ((lane >> 4) & 1) * 8 + (lane & 7)) * STRIDE
                       + 8 * ((lane >> 3) & 1);

    // sign constants: n bit7 = half -> q0; bit6 = nq>>1 -> q1; bit5 = nq&1 -> q2
    const float s0 = half ? -1.f : 1.f;
    const float s1 = (nq & 2) ? -1.f : 1.f;
    const float s2 = (nq & 1) ? -1.f : 1.f;

    const int s_mine  = t >> 1;       // sample row this thread builds (0..127)
    const int kg_mine = t & 1;        // which 128-k half this thread builds

    bool first = true;
    for (int tile = idx0; tile < NTILES; tile += NPERH) {
        // prefetch angles (two threads share one sample row)
        float xv[8];
        {
            const float* xp = x + (size_t)(tile * TILE_M + s_mine) * NQ;
#pragma unroll
            for (int q = 0; q < 8; q++) xv[q] = xp[q];
        }
        __syncthreads();              // prev tile MMA reads of m_sm done

        // ---- build m tile: thread t -> sample s_mine, k in [kg*128, +128) ----
        {
            float c[8], sn[8];
#pragma unroll
            for (int q = 0; q < 8; q++) {
                float sv, cv;
                __sincosf(0.5f * xv[q], &sv, &cv);
                c[q] = cv; sn[q] = sv;
            }
            float H16[16], L16[16];
#pragma unroll
            for (int h = 0; h < 16; h++)
                H16[h] = ((h & 8) ? sn[0] : c[0]) * ((h & 4) ? sn[1] : c[1])
                       * ((h & 2) ? sn[2] : c[2]) * ((h & 1) ? sn[3] : c[3]);
#pragma unroll
            for (int v = 0; v < 16; v++)
                L16[v] = ((v & 8) ? sn[4] : c[4]) * ((v & 4) ? sn[5] : c[5])
                       * ((v & 2) ? sn[6] : c[6]) * ((v & 1) ? sn[7] : c[7]);
            __half* mrow = m_sm + s_mine * STRIDE + kg_mine * 128;
            const int kbase = kg_mine * 128;
#pragma unroll
            for (int kk = 0; kk < 128; kk += 8) {
                const float hh = H16[(kbase + kk) >> 4];
                __half tmp[8];
#pragma unroll
                for (int e = 0; e < 8; e += 2) {
                    const __half2 h2 = __floats2half2_rn(hh * L16[(kk + e) & 15],
                                                         hh * L16[(kk + e + 1) & 15]);
                    *(__half2*)&tmp[e] = h2;
                }
                *(uint4*)(mrow + kk) = *(uint4*)tmp;
            }
        }
        if (first) { asm volatile("cp.async.wait_group 0;" ::: "memory"); first = false; }
        __syncthreads();

        // ---- K=256 mma loop, register double-buffered fragments ----
        float4 acc[4][8];
#pragma unroll
        for (int ms = 0; ms < 4; ms++)
#pragma unroll
            for (int nt = 0; nt < 8; nt++)
                acc[ms][nt] = make_float4(0.f, 0.f, 0.f, 0.f);

        uint32_t aF[2][4][4], bF[2][4][4];
#pragma unroll
        for (int ms = 0; ms < 4; ms++)
            ldsm4(aF[0][ms], m_u + (uint32_t)(rowA_off + ms * 16 * STRIDE) * 2u);
#pragma unroll
        for (int j = 0; j < 4; j++)
            ldsm4(bF[0][j], b_u + (uint32_t)(rowB_off + j * 16 * STRIDE) * 2u);

#pragma unroll
        for (int it = 0; it < 16; it++) {
            const int p = it & 1;
            if (it < 15) {
                const int kb = (it + 1) * 16;
#pragma unroll
                for (int ms = 0; ms < 4; ms++)
                    ldsm4(aF[p ^ 1][ms],
                          m_u + (uint32_t)(rowA_off + ms * 16 * STRIDE + kb) * 2u);
#pragma unroll
                for (int j = 0; j < 4; j++)
                    ldsm4(bF[p ^ 1][j],
                          b_u + (uint32_t)(rowB_off + j * 16 * STRIDE + kb) * 2u);
            }
#pragma unroll
            for (int ms = 0; ms < 4; ms++) {
#pragma unroll
                for (int j = 0; j < 4; j++) {
                    mma16816(acc[ms][2 * j],     aF[p][ms], bF[p][j][0], bF[p][j][1]);
                    mma16816(acc[ms][2 * j + 1], aF[p][ms], bF[p][j][2], bF[p][j][3]);
                }
            }
        }

        // ---- epilogue: T/S partial sums per ms into comb[nq][row][q] ----
        // (comb is a dedicated region; no sync needed against m_sm here)
#pragma unroll
        for (int ms = 0; ms < 4; ms++) {
            float Tlo = 0.f, S2lo = 0.f, S1lo = 0.f, S0lo = 0.f;
            float Thi = 0.f, S2hi = 0.f, S1hi = 0.f, S0hi = 0.f;
#pragma unroll
            for (int nt = 0; nt < 8; nt++) {
                const float4 cc = acc[ms][nt];
                const float plo = cc.x * cc.x + cc.y * cc.y;
                const float phi = cc.z * cc.z + cc.w * cc.w;
                Tlo += plo; Thi += phi;
                if (nt & 4) { S2lo += plo; S2hi += phi; }
                if (nt & 2) { S1lo += plo; S1hi += phi; }
                if (nt & 1) { S0lo += plo; S0hi += phi; }
            }
            float T6lo = (tig & 2) ? -Tlo : Tlo;
            float T7lo = (tig & 1) ? -Tlo : Tlo;
            float T6hi = (tig & 2) ? -Thi : Thi;
            float T7hi = (tig & 1) ? -Thi : Thi;

            const float rT  = red4(Tlo),  rT_h = red4(Thi);
            const float rS2 = red4(S2lo), rS2h = red4(S2hi);
            const float rS1 = red4(S1lo), rS1h = red4(S1hi);
            const float rS0 = red4(S0lo), rS0h = red4(S0hi);
            const float rT6 = red4(T6lo), rT6h = red4(T6hi);
            const float rT7 = red4(T7lo), rT7h = red4(T7hi);

            if (tig == 0) {
                const int rlo = mh * 64 + ms * 16 + gid;
                float* plo = comb + (nq * 128 + rlo) * 8;
                plo[0] = s0 * rT;  plo[1] = s1 * rT;  plo[2] = s2 * rT;
                plo[3] = rT - 2.f * rS2;
                plo[4] = rT - 2.f * rS1;
                plo[5] = rT - 2.f * rS0;
                plo[6] = rT6;      plo[7] = rT7;
                float* phi = comb + (nq * 128 + rlo + 8) * 8;
                phi[0] = s0 * rT_h; phi[1] = s1 * rT_h; phi[2] = s2 * rT_h;
                phi[3] = rT_h - 2.f * rS2h;
                phi[4] = rT_h - 2.f * rS1h;
                phi[5] = rT_h - 2.f * rS0h;
                phi[6] = rT6h;      phi[7] = rT7h;
            }
        }
        __syncthreads();

        // ---- merge 4 nq regions; 2 halves converge in global atomics ----
        {
            const int rr = t >> 1, qp = (t & 1) * 4;
            float a0 = 0.f, a1 = 0.f, a2 = 0.f, a3 = 0.f;
#pragma unroll
            for (int r2 = 0; r2 < 4; r2++) {
                const float* cp2 = comb + (r2 * 128 + rr) * 8 + qp;
                a0 += cp2[0]; a1 += cp2[1]; a2 += cp2[2]; a3 += cp2[3];
            }
            float* op = out + (size_t)(tile * TILE_M + rr) * NQ + qp;
            atomicAdd(op,     a0);
            atomicAdd(op + 1, a1);
            atomicAdd(op + 2, a2);
            atomicAdd(op + 3, a3);
        }
    }
}

// ---------------------------------------------------------------------------
extern "C" void kernel_launch(void* const* d_in, const int* in_sizes, int n_in,
                              void* d_out, int out_size) {
    const float* x = (const float*)d_in[0];
    const float* w = (const float*)d_in[1];
    if (n_in >= 2 && in_sizes[0] < in_sizes[1]) {
        const float* tmp = x; x = w; w = tmp;
    }
    float* out = (float*)d_out;

    cudaFuncSetAttribute(qsim_main_kernel,
                         cudaFuncAttributeMaxDynamicSharedMemorySize, SMEM_TOTAL);

    build_V_kernel<<<544, 256>>>(w, (float4*)out);
    qsim_main_kernel<<<2 * NPERH, THREADS, SMEM_TOTAL>>>(x, out);
}